// round 9
// baseline (speedup 1.0000x reference)
#include <cuda_runtime.h>
#include <cstdint>

#define Cc 64
#define CO 64
#define Ss 256
#define LL (Ss * Ss)

#define CHUNK 8        // channels per pipeline stage
#define NSTAGE 4       // ring slots
#define NCHUNK (Cc / CHUNK)   // 8 stages total
#define THREADS 320    // 2 producer warps + 8 consumer warps

// ---------------------------------------------------------------------------
// Warp-specialized fused Reverb kernel.
//   g[c,l]   = x[c,l] * sum_{i,j valid} w[c*9+i*3+j, (y+1-i)*S + (x+1-j)]
//   out[o,l] = sum_c conv[c,o] * g[c,l]
// Block owns 128 consecutive pixels (one half-row). Producer warps (8,9)
// stream the tap-gather into a 4-stage smem ring; consumer warps (0-7) run
// the register-tiled channel mix. Handoff via named counting barriers:
//   full  id 1+(s&3): producers arrive after STS, consumers sync before LDS
//   empty id 5+(s&3): consumers arrive after use, producers sync before reuse
// ---------------------------------------------------------------------------
__global__ __launch_bounds__(THREADS, 3) void reverb_ws_kernel(
    const float* __restrict__ x,      // (C, L)
    const float* __restrict__ w,      // (C*9, L)
    const float* __restrict__ conv,   // (C, CO)
    float* __restrict__ out)          // (CO, L)
{
    __shared__ __align__(16) float sconv[Cc * CO];                 // 16 KB
    __shared__ __align__(16) float ring[NSTAGE * CHUNK * 128];     // 16 KB

    const int tid = threadIdx.x;
    const int wid = tid >> 5;
    const int lane = tid & 31;

    // Everyone loads the conv table (4096 floats = 1024 float4)
    for (int i = tid; i < Cc * CO / 4; i += THREADS)
        ((float4*)sconv)[i] = ((const float4*)conv)[i];
    __syncthreads();

    const int lbase = blockIdx.x * 128;
    const int yb = lbase >> 8;
    const int xb = lbase & 255;

    if (wid >= 8) {
        // =================== PRODUCER (warps 8,9) ===================
        const int ptid = tid - 256;    // 0..63
        for (int s = 0; s < NCHUNK; s++) {
            if (s >= NSTAGE) {
                asm volatile("bar.sync %0, %1;" :: "r"(5 + (s & 3)), "n"(THREADS) : "memory");
            }
            float* dst = ring + (s & 3) * (CHUNK * 128);
            const int cbase = s * CHUNK;
#pragma unroll
            for (int k = 0; k < 4; k++) {
                const int id = ptid + 64 * k;       // 0..255 tasks
                const int cl = id >> 5;             // 0..7
                const int grp = id & 31;
                const int c = cbase + cl;
                const int x0 = xb + grp * 4;

                const float* wc = w + (size_t)c * 9 * LL;
                const float mL = (x0 == 0) ? 0.0f : 1.0f;
                const float mR = (x0 == Ss - 4) ? 0.0f : 1.0f;
                const int xL = (x0 == 0) ? 0 : x0 - 1;
                const int xR = (x0 == Ss - 4) ? Ss - 1 : x0 + 4;

                float ws0 = 0.f, ws1 = 0.f, ws2 = 0.f, ws3 = 0.f;
#pragma unroll
                for (int i = 0; i < 3; i++) {
                    const int ry = yb + 1 - i;
                    const bool vy = (unsigned)ry < (unsigned)Ss;
                    const float my = vy ? 1.0f : 0.0f;
                    const int ryc = vy ? ry : yb;
                    const int rowoff = ryc * Ss + x0;

                    const float* p0 = wc + (size_t)(i * 3 + 0) * LL + rowoff;
                    const float* p1 = wc + (size_t)(i * 3 + 1) * LL + rowoff;
                    const float* p2 = wc + (size_t)(i * 3 + 2) * LL + rowoff;

                    const float4 a = __ldg((const float4*)p0);
                    const float  rsc = mR * __ldg(p0 - x0 + xR);
                    const float4 b = __ldg((const float4*)p1);
                    const float  lsc = mL * __ldg(p2 - x0 + xL);
                    const float4 d = __ldg((const float4*)p2);

                    ws0 = fmaf(my, (a.y + b.x) + lsc, ws0);
                    ws1 = fmaf(my, (a.z + b.y) + d.x, ws1);
                    ws2 = fmaf(my, (a.w + b.z) + d.y, ws2);
                    ws3 = fmaf(my, (rsc + b.w) + d.z, ws3);
                }

                const float4 xv = __ldg((const float4*)(x + (size_t)c * LL + lbase + grp * 4));
                float4 gv;
                gv.x = xv.x * ws0;
                gv.y = xv.y * ws1;
                gv.z = xv.z * ws2;
                gv.w = xv.w * ws3;
                *(float4*)(dst + cl * 128 + grp * 4) = gv;
            }
            asm volatile("bar.arrive %0, %1;" :: "r"(1 + (s & 3)), "n"(THREADS) : "memory");
        }
    } else {
        // =================== CONSUMER (warps 0-7) ===================
        const int og = wid;            // 8 outputs [8og, 8og+8)

        unsigned long long acc[4][4];  // [o-pair][pixel]
#pragma unroll
        for (int op = 0; op < 4; op++)
#pragma unroll
            for (int p = 0; p < 4; p++) acc[op][p] = 0ull;

        for (int s = 0; s < NCHUNK; s++) {
            asm volatile("bar.sync %0, %1;" :: "r"(1 + (s & 3)), "n"(THREADS) : "memory");
            const float* src = ring + (s & 3) * (CHUNK * 128);
#pragma unroll
            for (int cl = 0; cl < CHUNK; cl++) {
                const int c = s * CHUNK + cl;
                const float4 g4 = *(const float4*)(src + cl * 128 + lane * 4);
                unsigned long long gp[4];
                asm("mov.b64 %0, {%1, %1};" : "=l"(gp[0]) : "f"(g4.x));
                asm("mov.b64 %0, {%1, %1};" : "=l"(gp[1]) : "f"(g4.y));
                asm("mov.b64 %0, {%1, %1};" : "=l"(gp[2]) : "f"(g4.z));
                asm("mov.b64 %0, {%1, %1};" : "=l"(gp[3]) : "f"(g4.w));

                const ulonglong2* cv = (const ulonglong2*)(sconv + c * CO + og * 8);
                const ulonglong2 cva = cv[0];
                const ulonglong2 cvb = cv[1];
#pragma unroll
                for (int p = 0; p < 4; p++) {
                    asm("fma.rn.f32x2 %0, %1, %2, %0;" : "+l"(acc[0][p]) : "l"(cva.x), "l"(gp[p]));
                    asm("fma.rn.f32x2 %0, %1, %2, %0;" : "+l"(acc[1][p]) : "l"(cva.y), "l"(gp[p]));
                    asm("fma.rn.f32x2 %0, %1, %2, %0;" : "+l"(acc[2][p]) : "l"(cvb.x), "l"(gp[p]));
                    asm("fma.rn.f32x2 %0, %1, %2, %0;" : "+l"(acc[3][p]) : "l"(cvb.y), "l"(gp[p]));
                }
            }
            asm volatile("bar.arrive %0, %1;" :: "r"(5 + (s & 3)), "n"(THREADS) : "memory");
        }

        // Epilogue: unpack, 8 coalesced STG.128 per warp
#pragma unroll
        for (int op = 0; op < 4; op++) {
            unsigned int lo[4], hi[4];
#pragma unroll
            for (int p = 0; p < 4; p++) {
                asm("mov.b64 {%0, %1}, %2;" : "=r"(lo[p]), "=r"(hi[p]) : "l"(acc[op][p]));
            }
            const int o = og * 8 + 2 * op;
            float4 v0, v1;
            v0.x = __uint_as_float(lo[0]); v0.y = __uint_as_float(lo[1]);
            v0.z = __uint_as_float(lo[2]); v0.w = __uint_as_float(lo[3]);
            v1.x = __uint_as_float(hi[0]); v1.y = __uint_as_float(hi[1]);
            v1.z = __uint_as_float(hi[2]); v1.w = __uint_as_float(hi[3]);
            *(float4*)(out + (size_t)o * LL + lbase + lane * 4) = v0;
            *(float4*)(out + (size_t)(o + 1) * LL + lbase + lane * 4) = v1;
        }
    }
}

extern "C" void kernel_launch(void* const* d_in, const int* in_sizes, int n_in,
                              void* d_out, int out_size) {
    const float* x    = (const float*)d_in[0];  // (1, C, S, S)
    const float* w    = (const float*)d_in[1];  // (1, C*9, L)
    const float* conv = (const float*)d_in[2];  // (C, CO)
    float* out = (float*)d_out;                 // (1, CO, S, S)

    reverb_ws_kernel<<<LL / 128, THREADS>>>(x, w, conv, out);
}

// round 10
// speedup vs baseline: 3.0771x; 3.0771x over previous
#include <cuda_runtime.h>
#include <cstdint>

#define Cc 64
#define CO 64
#define Ss 256
#define LL (Ss * Ss)

#define CHUNK 8               // channels per pipeline chunk
#define NCHUNK (Cc / CHUNK)   // 8 chunks

// ---------------------------------------------------------------------------
// Software-pipelined fused Reverb kernel (uniform warps, no specialization).
//   g[c,l]   = x[c,l] * sum_{i,j valid} w[c*9+i*3+j, (y+1-i)*S + (x+1-j)]
//   out[o,l] = sum_c conv[c,o] * g[c,l]
// Block owns 128 px. Per chunk of 8 channels, each thread computes one
// (channel, 4px) tap-gather task. Loads for chunk s+1 are front-issued
// (12 independent LDGs in registers) before the mix-FFMA loop of chunk s,
// hiding DRAM latency under compute. Double-buffered smem, 1 sync/chunk.
// ---------------------------------------------------------------------------
__global__ __launch_bounds__(256, 2) void reverb_pipe_kernel(
    const float* __restrict__ x,      // (C, L)
    const float* __restrict__ w,      // (C*9, L)
    const float* __restrict__ conv,   // (C, CO)
    float* __restrict__ out)          // (CO, L)
{
    __shared__ __align__(16) float sconv[Cc * CO];        // 16 KB
    __shared__ __align__(16) float sg[2][CHUNK * 128];    // 8 KB

    const int tid = threadIdx.x;
    const int wid = tid >> 5;
    const int lane = tid & 31;

    // conv table (first consumer use is after the first __syncthreads)
#pragma unroll
    for (int k = 0; k < 4; k++) {
        const int i = tid + 256 * k;
        ((float4*)sconv)[i] = ((const float4*)conv)[i];
    }

    const int lbase = blockIdx.x * 128;
    const int yb = lbase >> 8;
    const int xb = lbase & 255;

    // Per-thread tap task geometry (fixed across chunks): channel-slot = wid
    const int cl = wid;               // 0..7 channel within chunk
    const int grp = lane;             // 0..31 pixel group
    const int x0 = xb + grp * 4;

    const float mL = (x0 == 0) ? 0.0f : 1.0f;
    const float mR = (x0 == Ss - 4) ? 0.0f : 1.0f;
    const int xL = (x0 == 0) ? 0 : x0 - 1;
    const int xR = (x0 == Ss - 4) ? Ss - 1 : x0 + 4;

    // y masks / clamped rows: independent of channel -> hoisted
    float my[3];
    int rowoff[3];
#pragma unroll
    for (int i = 0; i < 3; i++) {
        const int ry = yb + 1 - i;
        const bool vy = (unsigned)ry < (unsigned)Ss;
        my[i] = vy ? 1.0f : 0.0f;
        rowoff[i] = (vy ? ry : yb) * Ss + x0;
    }

    // Front-batched load registers for one chunk
    float4 a[3], b[3], d[3], xv;
    float rs[3], ls[3];

    // ---- macro-ish lambda: issue all loads for chunk s (c = s*8 + cl) ----
    auto LOAD = [&](int s) {
        const int c = s * CHUNK + cl;
        const float* wc = w + (size_t)c * 9 * LL;
#pragma unroll
        for (int i = 0; i < 3; i++) {
            const float* p0 = wc + (size_t)(i * 3 + 0) * LL + rowoff[i];
            const float* p1 = wc + (size_t)(i * 3 + 1) * LL + rowoff[i];
            const float* p2 = wc + (size_t)(i * 3 + 2) * LL + rowoff[i];
            a[i] = __ldg((const float4*)p0);
            rs[i] = __ldg(p0 - x0 + xR);
            b[i] = __ldg((const float4*)p1);
            ls[i] = __ldg(p2 - x0 + xL);
            d[i] = __ldg((const float4*)p2);
        }
        xv = __ldg((const float4*)(x + (size_t)c * LL + lbase + grp * 4));
    };

    unsigned long long acc[4][4];     // [o-pair][pixel], round-8 layout
#pragma unroll
    for (int op = 0; op < 4; op++)
#pragma unroll
        for (int p = 0; p < 4; p++) acc[op][p] = 0ull;

    LOAD(0);

    for (int s = 0; s < NCHUNK; s++) {
        // ---- compute g for my task from front-batched regs ----
        float ws0 = 0.f, ws1 = 0.f, ws2 = 0.f, ws3 = 0.f;
#pragma unroll
        for (int i = 0; i < 3; i++) {
            ws0 = fmaf(my[i], (a[i].y + b[i].x) + mL * ls[i], ws0);
            ws1 = fmaf(my[i], (a[i].z + b[i].y) + d[i].x, ws1);
            ws2 = fmaf(my[i], (a[i].w + b[i].z) + d[i].y, ws2);
            ws3 = fmaf(my[i], (mR * rs[i] + b[i].w) + d[i].z, ws3);
        }
        float4 gv;
        gv.x = xv.x * ws0;
        gv.y = xv.y * ws1;
        gv.z = xv.z * ws2;
        gv.w = xv.w * ws3;
        *(float4*)(&sg[s & 1][cl * 128 + grp * 4]) = gv;

        __syncthreads();   // chunk s staged (also orders sconv on s==0)

        if (s + 1 < NCHUNK) LOAD(s + 1);   // front-issue next chunk's loads

        // ---- mix chunk s from smem (round-8 inner loop) ----
        const float* src = sg[s & 1];
        const int og = wid;            // warp owns outputs [8og, 8og+8)
#pragma unroll
        for (int c2 = 0; c2 < CHUNK; c2++) {
            const int c = s * CHUNK + c2;
            const float4 g4 = *(const float4*)(src + c2 * 128 + lane * 4);
            unsigned long long gp[4];
            asm("mov.b64 %0, {%1, %1};" : "=l"(gp[0]) : "f"(g4.x));
            asm("mov.b64 %0, {%1, %1};" : "=l"(gp[1]) : "f"(g4.y));
            asm("mov.b64 %0, {%1, %1};" : "=l"(gp[2]) : "f"(g4.z));
            asm("mov.b64 %0, {%1, %1};" : "=l"(gp[3]) : "f"(g4.w));

            const ulonglong2* cv = (const ulonglong2*)(sconv + c * CO + og * 8);
            const ulonglong2 cva = cv[0];
            const ulonglong2 cvb = cv[1];
#pragma unroll
            for (int p = 0; p < 4; p++) {
                asm("fma.rn.f32x2 %0, %1, %2, %0;" : "+l"(acc[0][p]) : "l"(cva.x), "l"(gp[p]));
                asm("fma.rn.f32x2 %0, %1, %2, %0;" : "+l"(acc[1][p]) : "l"(cva.y), "l"(gp[p]));
                asm("fma.rn.f32x2 %0, %1, %2, %0;" : "+l"(acc[2][p]) : "l"(cvb.x), "l"(gp[p]));
                asm("fma.rn.f32x2 %0, %1, %2, %0;" : "+l"(acc[3][p]) : "l"(cvb.y), "l"(gp[p]));
            }
        }
        // No second sync needed: next STS targets the other buffer, and the
        // buffer being overwritten two chunks later is protected by the
        // intervening __syncthreads.
    }

    // ---- Epilogue: unpack, 8 coalesced STG.128 per warp ----
    const int og = wid;
#pragma unroll
    for (int op = 0; op < 4; op++) {
        unsigned int lo[4], hi[4];
#pragma unroll
        for (int p = 0; p < 4; p++) {
            asm("mov.b64 {%0, %1}, %2;" : "=r"(lo[p]), "=r"(hi[p]) : "l"(acc[op][p]));
        }
        const int o = og * 8 + 2 * op;
        float4 v0, v1;
        v0.x = __uint_as_float(lo[0]); v0.y = __uint_as_float(lo[1]);
        v0.z = __uint_as_float(lo[2]); v0.w = __uint_as_float(lo[3]);
        v1.x = __uint_as_float(hi[0]); v1.y = __uint_as_float(hi[1]);
        v1.z = __uint_as_float(hi[2]); v1.w = __uint_as_float(hi[3]);
        *(float4*)(out + (size_t)o * LL + lbase + lane * 4) = v0;
        *(float4*)(out + (size_t)(o + 1) * LL + lbase + lane * 4) = v1;
    }
}

extern "C" void kernel_launch(void* const* d_in, const int* in_sizes, int n_in,
                              void* d_out, int out_size) {
    const float* x    = (const float*)d_in[0];  // (1, C, S, S)
    const float* w    = (const float*)d_in[1];  // (1, C*9, L)
    const float* conv = (const float*)d_in[2];  // (C, CO)
    float* out = (float*)d_out;                 // (1, CO, S, S)

    reverb_pipe_kernel<<<LL / 128, 256>>>(x, w, conv, out);
}

// round 11
// speedup vs baseline: 3.4339x; 1.1159x over previous
#include <cuda_runtime.h>
#include <cstdint>

#define Cc 64
#define CO 64
#define Ss 256
#define LL (Ss * Ss)

#define CHUNK 8               // channels per pipeline chunk
#define NCHUNK (Cc / CHUNK)   // 8 chunks

// ---------------------------------------------------------------------------
// Software-pipelined fused Reverb kernel (uniform warps).
//   g[c,l]   = x[c,l] * sum_{i,j valid} w[c*9+i*3+j, (y+1-i)*S + (x+1-j)]
//   out[o,l] = sum_c conv[c,o] * g[c,l]
// Block owns 128 px. Per chunk of 8 channels each thread computes one
// (channel, 4px) tap-gather task from 10 front-issued independent loads
// (9 float4 planes + x; boundary scalars come from warp shuffles, with
// real loads only on lanes 0/31). Loads for chunk s+1 are issued BEFORE
// the barrier so barrier-wait time also hides latency. Double-buffered
// smem, 1 sync/chunk; register-tiled mix (round-8 layout).
// ---------------------------------------------------------------------------
__global__ __launch_bounds__(256, 2) void reverb_pipe_kernel(
    const float* __restrict__ x,      // (C, L)
    const float* __restrict__ w,      // (C*9, L)
    const float* __restrict__ conv,   // (C, CO)
    float* __restrict__ out)          // (CO, L)
{
    __shared__ __align__(16) float sconv[Cc * CO];        // 16 KB
    __shared__ __align__(16) float sg[2][CHUNK * 128];    // 8 KB

    const int tid = threadIdx.x;
    const int wid = tid >> 5;
    const int lane = tid & 31;

    // conv table (first consumer use is after the first __syncthreads)
#pragma unroll
    for (int k = 0; k < 4; k++) {
        const int i = tid + 256 * k;
        ((float4*)sconv)[i] = ((const float4*)conv)[i];
    }

    const int lbase = blockIdx.x * 128;
    const int yb = lbase >> 8;
    const int xb = lbase & 255;

    // Per-thread tap task geometry (fixed across chunks)
    const int cl = wid;               // channel slot within chunk
    const int grp = lane;             // pixel group (4 px)
    const int x0 = xb + grp * 4;

    // Edge-lane scalar loads: lane 0 needs plane-j2 @ x0-1 (valid unless x0==0),
    // lane 31 needs plane-j0 @ x0+4 (valid unless x0==252).
    const bool edgeL = (lane == 0) && (x0 != 0);
    const bool edgeR = (lane == 31) && (x0 != Ss - 4);

    // y masks / clamped rows: channel-independent -> hoisted
    float my[3];
    int rowoff[3];
#pragma unroll
    for (int i = 0; i < 3; i++) {
        const int ry = yb + 1 - i;
        const bool vy = (unsigned)ry < (unsigned)Ss;
        my[i] = vy ? 1.0f : 0.0f;
        rowoff[i] = (vy ? ry : yb) * Ss + x0;
    }

    // Front-batched load registers for one chunk
    float4 a[3], b[3], d[3], xv;
    float le[3], re[3];   // edge scalars (lanes 0/31 only, pre-masked)

    auto LOAD = [&](int s) {
        const int c = s * CHUNK + cl;
        const float* wc = w + (size_t)c * 9 * LL;
#pragma unroll
        for (int i = 0; i < 3; i++) {
            const float* p0 = wc + (size_t)(i * 3 + 0) * LL + rowoff[i];
            const float* p1 = wc + (size_t)(i * 3 + 1) * LL + rowoff[i];
            const float* p2 = wc + (size_t)(i * 3 + 2) * LL + rowoff[i];
            a[i] = __ldg((const float4*)p0);
            b[i] = __ldg((const float4*)p1);
            d[i] = __ldg((const float4*)p2);
            le[i] = edgeL ? __ldg(p2 - 1) : 0.0f;   // predicated off except lane 0
            re[i] = edgeR ? __ldg(p0 + 4) : 0.0f;   // predicated off except lane 31
        }
        xv = __ldg((const float4*)(x + (size_t)c * LL + lbase + grp * 4));
    };

    unsigned long long acc[4][4];     // [o-pair][pixel]
#pragma unroll
    for (int op = 0; op < 4; op++)
#pragma unroll
        for (int p = 0; p < 4; p++) acc[op][p] = 0ull;

    LOAD(0);

    for (int s = 0; s < NCHUNK; s++) {
        // ---- compute g for my task from front-batched regs + shuffles ----
        float ws0 = 0.f, ws1 = 0.f, ws2 = 0.f, ws3 = 0.f;
#pragma unroll
        for (int i = 0; i < 3; i++) {
            // left scalar (plane j2 @ x0-1): neighbor lane's d.w
            float lsv = __shfl_up_sync(0xffffffffu, d[i].w, 1);
            if (lane == 0) lsv = le[i];
            // right scalar (plane j0 @ x0+4): neighbor lane's a.x
            float rsv = __shfl_down_sync(0xffffffffu, a[i].x, 1);
            if (lane == 31) rsv = re[i];

            ws0 = fmaf(my[i], (a[i].y + b[i].x) + lsv, ws0);
            ws1 = fmaf(my[i], (a[i].z + b[i].y) + d[i].x, ws1);
            ws2 = fmaf(my[i], (a[i].w + b[i].z) + d[i].y, ws2);
            ws3 = fmaf(my[i], (rsv + b[i].w) + d[i].z, ws3);
        }
        float4 gv;
        gv.x = xv.x * ws0;
        gv.y = xv.y * ws1;
        gv.z = xv.z * ws2;
        gv.w = xv.w * ws3;
        *(float4*)(&sg[s & 1][cl * 128 + grp * 4]) = gv;

        // Front-issue next chunk's loads BEFORE the barrier so the wait
        // itself hides their latency.
        if (s + 1 < NCHUNK) LOAD(s + 1);

        __syncthreads();   // chunk s staged (also orders sconv on s==0)

        // ---- mix chunk s from smem ----
        const float* src = sg[s & 1];
        const int og = wid;            // warp owns outputs [8og, 8og+8)
#pragma unroll
        for (int c2 = 0; c2 < CHUNK; c2++) {
            const int c = s * CHUNK + c2;
            const float4 g4 = *(const float4*)(src + c2 * 128 + lane * 4);
            unsigned long long gp[4];
            asm("mov.b64 %0, {%1, %1};" : "=l"(gp[0]) : "f"(g4.x));
            asm("mov.b64 %0, {%1, %1};" : "=l"(gp[1]) : "f"(g4.y));
            asm("mov.b64 %0, {%1, %1};" : "=l"(gp[2]) : "f"(g4.z));
            asm("mov.b64 %0, {%1, %1};" : "=l"(gp[3]) : "f"(g4.w));

            const ulonglong2* cv = (const ulonglong2*)(sconv + c * CO + og * 8);
            const ulonglong2 cva = cv[0];
            const ulonglong2 cvb = cv[1];
#pragma unroll
            for (int p = 0; p < 4; p++) {
                asm("fma.rn.f32x2 %0, %1, %2, %0;" : "+l"(acc[0][p]) : "l"(cva.x), "l"(gp[p]));
                asm("fma.rn.f32x2 %0, %1, %2, %0;" : "+l"(acc[1][p]) : "l"(cva.y), "l"(gp[p]));
                asm("fma.rn.f32x2 %0, %1, %2, %0;" : "+l"(acc[2][p]) : "l"(cvb.x), "l"(gp[p]));
                asm("fma.rn.f32x2 %0, %1, %2, %0;" : "+l"(acc[3][p]) : "l"(cvb.y), "l"(gp[p]));
            }
        }
        // Double buffering + the per-iteration barrier protect the ring.
    }

    // ---- Epilogue: unpack, 8 coalesced STG.128 per warp ----
    const int og = wid;
#pragma unroll
    for (int op = 0; op < 4; op++) {
        unsigned int lo[4], hi[4];
#pragma unroll
        for (int p = 0; p < 4; p++) {
            asm("mov.b64 {%0, %1}, %2;" : "=r"(lo[p]), "=r"(hi[p]) : "l"(acc[op][p]));
        }
        const int o = og * 8 + 2 * op;
        float4 v0, v1;
        v0.x = __uint_as_float(lo[0]); v0.y = __uint_as_float(lo[1]);
        v0.z = __uint_as_float(lo[2]); v0.w = __uint_as_float(lo[3]);
        v1.x = __uint_as_float(hi[0]); v1.y = __uint_as_float(hi[1]);
        v1.z = __uint_as_float(hi[2]); v1.w = __uint_as_float(hi[3]);
        *(float4*)(out + (size_t)o * LL + lbase + lane * 4) = v0;
        *(float4*)(out + (size_t)(o + 1) * LL + lbase + lane * 4) = v1;
    }
}

extern "C" void kernel_launch(void* const* d_in, const int* in_sizes, int n_in,
                              void* d_out, int out_size) {
    const float* x    = (const float*)d_in[0];  // (1, C, S, S)
    const float* w    = (const float*)d_in[1];  // (1, C*9, L)
    const float* conv = (const float*)d_in[2];  // (C, CO)
    float* out = (float*)d_out;                 // (1, CO, S, S)

    reverb_pipe_kernel<<<LL / 128, 256>>>(x, w, conv, out);
}